// round 16
// baseline (speedup 1.0000x reference)
#include <cuda_runtime.h>
#include <math.h>

#define N_IN   512
#define N_OUT  10
#define D_OUT  16
#define D_IN   8
#define NJD    (N_OUT * D_OUT)    // 160 output elements -> 160 blocks
#define NWARP  8
#define NTHR   (NWARP * 32)       // 256 threads
#define N_PER_WARP (N_IN / NWARP) // 64 n-rows per warp
#define EPS    1e-7f

// FINAL — converged kernel (session: 11.0 -> 6.66 us, 1.65x).
// One block per output element (j,d), 8 warps, no inter-block communication.
// Lane mapping: pair = lane>>1 (0..15) selects n-row offset, half = lane&1
// selects k-half. Warp w covers n in [w*64, (w+1)*64) striding 16:
// 4 iterations * (1 W float4 + 1 x float4) = 8 independent LDG.128 per lane
// -> single memory-latency exposure. W (2.6 MB) read exactly once chip-wide,
// L2-resident across graph replays. All pipes <2% busy; remaining wall time
// is graph-replay/launch overhead + one memory round-trip + run-to-run noise
// (measured band 6.656-6.88 us across identical binaries).
__global__ __launch_bounds__(NTHR) void digitcaps_per_jd(
    const float* __restrict__ x,   // (512, 8)
    const float* __restrict__ W,   // (512, 160, 8) contiguous
    float* __restrict__ out)       // 160 floats
{
    __shared__ float s_warp[NWARP];

    const int jd   = blockIdx.x;          // 0..159
    const int warp = threadIdx.x >> 5;    // 0..7
    const int lane = threadIdx.x & 31;
    const int pair = lane >> 1;           // 0..15
    const int half = lane & 1;            // 0..1

    const int n0 = warp * N_PER_WARP + pair;

    // Batch all 8 loads (independent addresses).
    float4 w4[4], x4[4];
#pragma unroll
    for (int i = 0; i < 4; ++i) {
        const int n = n0 + i * 16;
        w4[i] = *reinterpret_cast<const float4*>(
            W + ((size_t)n * NJD + jd) * D_IN + half * 4);
        x4[i] = *reinterpret_cast<const float4*>(
            x + (size_t)n * D_IN + half * 4);
    }

    // Two independent accumulator chains -> half the FMA dependency depth.
    float acc0 = 0.0f, acc1 = 0.0f;
#pragma unroll
    for (int i = 0; i < 4; i += 2) {
        acc0 = fmaf(w4[i].x,   x4[i].x,   acc0);
        acc0 = fmaf(w4[i].y,   x4[i].y,   acc0);
        acc0 = fmaf(w4[i].z,   x4[i].z,   acc0);
        acc0 = fmaf(w4[i].w,   x4[i].w,   acc0);
        acc1 = fmaf(w4[i+1].x, x4[i+1].x, acc1);
        acc1 = fmaf(w4[i+1].y, x4[i+1].y, acc1);
        acc1 = fmaf(w4[i+1].z, x4[i+1].z, acc1);
        acc1 = fmaf(w4[i+1].w, x4[i+1].w, acc1);
    }
    float acc = acc0 + acc1;

    // warp butterfly reduce (16 n-rows x 2 k-halves)
#pragma unroll
    for (int off = 16; off > 0; off >>= 1)
        acc += __shfl_xor_sync(0xFFFFFFFFu, acc, off);

    if (lane == 0) s_warp[warp] = acc;
    __syncthreads();

    // warp 0 finishes: lanes 0-7 pick up the 8 warp partials, 3-level shfl,
    // lane 0 applies squash (elementwise: the reference's last-axis sum is
    // over a size-1 axis) and stores.
    if (warp == 0) {
        float s = (lane < NWARP) ? s_warp[lane] : 0.0f;
#pragma unroll
        for (int off = 4; off > 0; off >>= 1)
            s += __shfl_xor_sync(0xFFFFFFFFu, s, off);

        if (lane == 0) {
            s *= (1.0f / (float)N_IN);
            const float sq   = s * s;
            const float norm = s / (sqrtf(sq + EPS) + EPS);
            out[jd] = (sq / (1.0f + sq)) * norm;
        }
    }
}

extern "C" void kernel_launch(void* const* d_in, const int* in_sizes, int n_in,
                              void* d_out, int out_size)
{
    const float* x;
    const float* W;
    if (in_sizes[0] == N_IN * D_IN) {
        x = (const float*)d_in[0];
        W = (const float*)d_in[1];
    } else {
        x = (const float*)d_in[1];
        W = (const float*)d_in[0];
    }
    float* out = (float*)d_out;

    digitcaps_per_jd<<<NJD, NTHR>>>(x, W, out);
}

// round 17
// speedup vs baseline: 1.0485x; 1.0485x over previous
#include <cuda_runtime.h>
#include <math.h>

#define N_IN   512
#define N_OUT  10
#define D_OUT  16
#define D_IN   8
#define NJD    (N_OUT * D_OUT)    // 160 output elements -> 160 blocks
#define NWARP  8
#define NTHR   (NWARP * 32)       // 256 threads
#define N_PER_WARP (N_IN / NWARP) // 64 n-rows per warp
#define EPS    1e-7f

// FINAL — converged kernel (session: 11.0 -> 6.66 us, 1.65x).
// One block per output element (j,d), 8 warps, no inter-block communication.
// Lane mapping: pair = lane>>1 (0..15) selects n-row offset, half = lane&1
// selects k-half. Warp w covers n in [w*64, (w+1)*64) striding 16:
// 4 iterations * (1 W float4 + 1 x float4) = 8 independent LDG.128 per lane
// -> single memory-latency exposure. W (2.6 MB) read exactly once chip-wide,
// L2-resident across graph replays. All pipes <2% busy; remaining wall time
// is graph-replay/launch overhead + one memory round-trip + run-to-run noise
// (measured band 6.656-6.91 us over 8 identical-source samples).
__global__ __launch_bounds__(NTHR) void digitcaps_per_jd(
    const float* __restrict__ x,   // (512, 8)
    const float* __restrict__ W,   // (512, 160, 8) contiguous
    float* __restrict__ out)       // 160 floats
{
    __shared__ float s_warp[NWARP];

    const int jd   = blockIdx.x;          // 0..159
    const int warp = threadIdx.x >> 5;    // 0..7
    const int lane = threadIdx.x & 31;
    const int pair = lane >> 1;           // 0..15
    const int half = lane & 1;            // 0..1

    const int n0 = warp * N_PER_WARP + pair;

    // Batch all 8 loads (independent addresses).
    float4 w4[4], x4[4];
#pragma unroll
    for (int i = 0; i < 4; ++i) {
        const int n = n0 + i * 16;
        w4[i] = *reinterpret_cast<const float4*>(
            W + ((size_t)n * NJD + jd) * D_IN + half * 4);
        x4[i] = *reinterpret_cast<const float4*>(
            x + (size_t)n * D_IN + half * 4);
    }

    // Two independent accumulator chains -> half the FMA dependency depth.
    float acc0 = 0.0f, acc1 = 0.0f;
#pragma unroll
    for (int i = 0; i < 4; i += 2) {
        acc0 = fmaf(w4[i].x,   x4[i].x,   acc0);
        acc0 = fmaf(w4[i].y,   x4[i].y,   acc0);
        acc0 = fmaf(w4[i].z,   x4[i].z,   acc0);
        acc0 = fmaf(w4[i].w,   x4[i].w,   acc0);
        acc1 = fmaf(w4[i+1].x, x4[i+1].x, acc1);
        acc1 = fmaf(w4[i+1].y, x4[i+1].y, acc1);
        acc1 = fmaf(w4[i+1].z, x4[i+1].z, acc1);
        acc1 = fmaf(w4[i+1].w, x4[i+1].w, acc1);
    }
    float acc = acc0 + acc1;

    // warp butterfly reduce (16 n-rows x 2 k-halves)
#pragma unroll
    for (int off = 16; off > 0; off >>= 1)
        acc += __shfl_xor_sync(0xFFFFFFFFu, acc, off);

    if (lane == 0) s_warp[warp] = acc;
    __syncthreads();

    // warp 0 finishes: lanes 0-7 pick up the 8 warp partials, 3-level shfl,
    // lane 0 applies squash (elementwise: the reference's last-axis sum is
    // over a size-1 axis) and stores.
    if (warp == 0) {
        float s = (lane < NWARP) ? s_warp[lane] : 0.0f;
#pragma unroll
        for (int off = 4; off > 0; off >>= 1)
            s += __shfl_xor_sync(0xFFFFFFFFu, s, off);

        if (lane == 0) {
            s *= (1.0f / (float)N_IN);
            const float sq   = s * s;
            const float norm = s / (sqrtf(sq + EPS) + EPS);
            out[jd] = (sq / (1.0f + sq)) * norm;
        }
    }
}

extern "C" void kernel_launch(void* const* d_in, const int* in_sizes, int n_in,
                              void* d_out, int out_size)
{
    const float* x;
    const float* W;
    if (in_sizes[0] == N_IN * D_IN) {
        x = (const float*)d_in[0];
        W = (const float*)d_in[1];
    } else {
        x = (const float*)d_in[1];
        W = (const float*)d_in[0];
    }
    float* out = (float*)d_out;

    digitcaps_per_jd<<<NJD, NTHR>>>(x, W, out);
}